// round 1
// baseline (speedup 1.0000x reference)
#include <cuda_runtime.h>
#include <math.h>

#define HID 1024
#define NHEAD 16
#define HDIM 64
#define BATCH 2
#define SEQ 2048
#define M_TOT (BATCH * SEQ)     // 4096
#define N_QKV (3 * HID)         // 3072

// Scratch (allocation-free rule: __device__ globals)
__device__ float g_qkv[M_TOT * N_QKV];   // 48 MB
__device__ float g_att[(size_t)M_TOT * HID];     // 16 MB

// ---------------------------------------------------------------------------
// SGEMM (NT): C[M,N] = A[M,K] @ B[N,K]^T + bias[N]
// 128x128 tile, BK=16, 256 threads, 8x8 register micro-tile per thread.
// ---------------------------------------------------------------------------
__global__ void __launch_bounds__(256) sgemm_nt_bias(
    const float* __restrict__ A, const float* __restrict__ Bm,
    const float* __restrict__ bias, float* __restrict__ C,
    int M, int N, int K)
{
    const int BM = 128, BN = 128, BK = 16;
    __shared__ float As[16][128];
    __shared__ float Bs[16][128];

    const int tid = threadIdx.x;
    const int tx = tid & 15;        // 0..15 -> N direction
    const int ty = tid >> 4;        // 0..15 -> M direction
    const int m0 = blockIdx.y * BM;
    const int n0 = blockIdx.x * BN;

    float acc[8][8];
#pragma unroll
    for (int i = 0; i < 8; i++)
#pragma unroll
        for (int j = 0; j < 8; j++) acc[i][j] = 0.f;

    const float* Ag = A + (size_t)m0 * K;
    const float* Bg = Bm + (size_t)n0 * K;

    for (int k0 = 0; k0 < K; k0 += BK) {
#pragma unroll
        for (int p = 0; p < 2; p++) {
            int idx = tid + p * 256;       // 0..511
            int row = idx >> 2;            // 0..127
            int kc  = (idx & 3) << 2;      // 0,4,8,12
            float4 va = *(const float4*)(Ag + (size_t)row * K + k0 + kc);
            As[kc + 0][row] = va.x;
            As[kc + 1][row] = va.y;
            As[kc + 2][row] = va.z;
            As[kc + 3][row] = va.w;
            float4 vb = *(const float4*)(Bg + (size_t)row * K + k0 + kc);
            Bs[kc + 0][row] = vb.x;
            Bs[kc + 1][row] = vb.y;
            Bs[kc + 2][row] = vb.z;
            Bs[kc + 3][row] = vb.w;
        }
        __syncthreads();

#pragma unroll
        for (int k = 0; k < BK; k++) {
            float a[8], b[8];
            *(float4*)(a)     = *(const float4*)&As[k][ty * 8];
            *(float4*)(a + 4) = *(const float4*)&As[k][ty * 8 + 4];
            *(float4*)(b)     = *(const float4*)&Bs[k][tx * 8];
            *(float4*)(b + 4) = *(const float4*)&Bs[k][tx * 8 + 4];
#pragma unroll
            for (int i = 0; i < 8; i++)
#pragma unroll
                for (int j = 0; j < 8; j++)
                    acc[i][j] += a[i] * b[j];
        }
        __syncthreads();
    }

    float bb[8];
#pragma unroll
    for (int j = 0; j < 8; j++) bb[j] = bias[n0 + tx * 8 + j];

#pragma unroll
    for (int i = 0; i < 8; i++) {
        float* Crow = C + (size_t)(m0 + ty * 8 + i) * N + n0 + tx * 8;
        float4 v0 = make_float4(acc[i][0] + bb[0], acc[i][1] + bb[1],
                                acc[i][2] + bb[2], acc[i][3] + bb[3]);
        float4 v1 = make_float4(acc[i][4] + bb[4], acc[i][5] + bb[5],
                                acc[i][6] + bb[6], acc[i][7] + bb[7]);
        *(float4*)(Crow)     = v0;
        *(float4*)(Crow + 4) = v1;
    }
}

// ---------------------------------------------------------------------------
// Flash attention, fp32. One CTA = one (b, h, 64-row Q tile).
// smem tiles (PAD=68 keeps float4 alignment): Qs/Ks transposed [d][row],
// Vs [j][d], Ps [j][i]. Online softmax with 16-lane shuffle reductions.
// ---------------------------------------------------------------------------
#define PAD 68

__global__ void __launch_bounds__(256) attn_kernel(
    const float* __restrict__ qkv, float* __restrict__ out)
{
    extern __shared__ float sm[];
    float (*Qs)[PAD] = (float(*)[PAD])(sm);
    float (*Ks)[PAD] = (float(*)[PAD])(sm + 64 * PAD);
    float (*Vs)[PAD] = (float(*)[PAD])(sm + 2 * 64 * PAD);
    float (*Ps)[PAD] = (float(*)[PAD])(sm + 3 * 64 * PAD);

    const int tid = threadIdx.x;
    const int tx = tid & 15;    // -> key (for S) / head-dim (for O) direction
    const int ty = tid >> 4;    // -> query-row direction
    const int bh = blockIdx.y;
    const int b = bh >> 4, h = bh & 15;
    const int q0 = blockIdx.x * 64;
    const float scale = 0.125f;  // 1/sqrt(64)

    const float* base = qkv + (size_t)b * SEQ * N_QKV + h * HDIM;
    const float* Qg = base;
    const float* Kg = base + HID;
    const float* Vg = base + 2 * HID;

    // Load Q tile transposed: Qs[d][i] = Q[q0+i][d] * scale
#pragma unroll
    for (int p = 0; p < 4; p++) {
        int idx = tid + p * 256;       // 0..1023
        int i  = idx >> 4;             // 0..63
        int d4 = (idx & 15) << 2;      // 0..60
        float4 v = *(const float4*)(Qg + (size_t)(q0 + i) * N_QKV + d4);
        Qs[d4 + 0][i] = v.x * scale;
        Qs[d4 + 1][i] = v.y * scale;
        Qs[d4 + 2][i] = v.z * scale;
        Qs[d4 + 3][i] = v.w * scale;
    }

    float m[4], l[4], o[4][4];
#pragma unroll
    for (int ii = 0; ii < 4; ii++) {
        m[ii] = -1e30f;
        l[ii] = 0.f;
#pragma unroll
        for (int jj = 0; jj < 4; jj++) o[ii][jj] = 0.f;
    }

    for (int kt = 0; kt < SEQ / 64; kt++) {
        __syncthreads();   // protect Ks/Vs/Ps reuse (and Qs store on iter 0)
        const int j0 = kt * 64;
#pragma unroll
        for (int p = 0; p < 4; p++) {
            int idx = tid + p * 256;
            int j  = idx >> 4;
            int d4 = (idx & 15) << 2;
            float4 v = *(const float4*)(Kg + (size_t)(j0 + j) * N_QKV + d4);
            Ks[d4 + 0][j] = v.x;
            Ks[d4 + 1][j] = v.y;
            Ks[d4 + 2][j] = v.z;
            Ks[d4 + 3][j] = v.w;
            float4 w = *(const float4*)(Vg + (size_t)(j0 + j) * N_QKV + d4);
            *(float4*)&Vs[j][d4] = w;
        }
        __syncthreads();

        // S = (Q*scale) @ K^T : 4x4 micro-tile per thread
        float s[4][4];
#pragma unroll
        for (int ii = 0; ii < 4; ii++)
#pragma unroll
            for (int jj = 0; jj < 4; jj++) s[ii][jj] = 0.f;

#pragma unroll
        for (int d = 0; d < 64; d++) {
            float qa[4], kb[4];
            *(float4*)qa = *(const float4*)&Qs[d][ty * 4];
            *(float4*)kb = *(const float4*)&Ks[d][tx * 4];
#pragma unroll
            for (int ii = 0; ii < 4; ii++)
#pragma unroll
                for (int jj = 0; jj < 4; jj++)
                    s[ii][jj] += qa[ii] * kb[jj];
        }

        // Online softmax per query row (row spread over 16 lanes in tx)
#pragma unroll
        for (int ii = 0; ii < 4; ii++) {
            float tmax = fmaxf(fmaxf(s[ii][0], s[ii][1]), fmaxf(s[ii][2], s[ii][3]));
#pragma unroll
            for (int off = 8; off; off >>= 1)
                tmax = fmaxf(tmax, __shfl_xor_sync(0xffffffffu, tmax, off));
            float mn = fmaxf(m[ii], tmax);
            float alpha = __expf(m[ii] - mn);
            m[ii] = mn;
            float rs = 0.f;
#pragma unroll
            for (int jj = 0; jj < 4; jj++) {
                float pij = __expf(s[ii][jj] - mn);
                s[ii][jj] = pij;
                rs += pij;
            }
#pragma unroll
            for (int off = 8; off; off >>= 1)
                rs += __shfl_xor_sync(0xffffffffu, rs, off);
            l[ii] = l[ii] * alpha + rs;
#pragma unroll
            for (int jj = 0; jj < 4; jj++) o[ii][jj] *= alpha;
            // store P transposed: Ps[j][i]
#pragma unroll
            for (int jj = 0; jj < 4; jj++)
                Ps[tx * 4 + jj][ty * 4 + ii] = s[ii][jj];
        }
        __syncthreads();

        // O += P @ V  (inner over j)
#pragma unroll
        for (int j = 0; j < 64; j++) {
            float pa[4], vb[4];
            *(float4*)pa = *(const float4*)&Ps[j][ty * 4];
            *(float4*)vb = *(const float4*)&Vs[j][tx * 4];
#pragma unroll
            for (int ii = 0; ii < 4; ii++)
#pragma unroll
                for (int jj = 0; jj < 4; jj++)
                    o[ii][jj] += pa[ii] * vb[jj];
        }
    }

    // Finalize and write in [b, l, h, d] layout
#pragma unroll
    for (int ii = 0; ii < 4; ii++) {
        float inv = 1.f / l[ii];
        int row = q0 + ty * 4 + ii;
        float* op = out + ((size_t)(b * SEQ + row)) * HID + h * HDIM + tx * 4;
        float4 r = make_float4(o[ii][0] * inv, o[ii][1] * inv,
                               o[ii][2] * inv, o[ii][3] * inv);
        *(float4*)op = r;
    }
}

// ---------------------------------------------------------------------------
// Launch
// ---------------------------------------------------------------------------
extern "C" void kernel_launch(void* const* d_in, const int* in_sizes, int n_in,
                              void* d_out, int out_size)
{
    // Match inputs by element count (all distinct) for robustness.
    const float *x = nullptr, *w_qkv = nullptr, *b_qkv = nullptr,
                *w_out = nullptr, *b_out = nullptr;
    for (int i = 0; i < n_in; i++) {
        const float* p = (const float*)d_in[i];
        switch (in_sizes[i]) {
            case M_TOT * HID:        x = p; break;       // 4,194,304
            case N_QKV * HID:        w_qkv = p; break;   // 3,145,728
            case N_QKV:              b_qkv = p; break;   // 3,072
            case HID * HID:          w_out = p; break;   // 1,048,576
            case HID:                b_out = p; break;   // 1,024
        }
    }
    float* out = (float*)d_out;

    float* qkv_buf = nullptr;
    float* att_buf = nullptr;
    cudaGetSymbolAddress((void**)&qkv_buf, g_qkv);
    cudaGetSymbolAddress((void**)&att_buf, g_att);

    const int smem = 4 * 64 * PAD * (int)sizeof(float);  // 69,632 B
    cudaFuncSetAttribute(attn_kernel,
                         cudaFuncAttributeMaxDynamicSharedMemorySize, smem);

    dim3 blk(256);
    // GEMM1: qkv = x @ w_qkv^T + b_qkv   [4096, 3072]
    sgemm_nt_bias<<<dim3(N_QKV / 128, M_TOT / 128), blk>>>(
        x, w_qkv, b_qkv, qkv_buf, M_TOT, N_QKV, HID);

    // Attention: 32 q-tiles x 32 (b,h)
    attn_kernel<<<dim3(SEQ / 64, BATCH * NHEAD), blk, smem>>>(qkv_buf, att_buf);

    // GEMM2: out = att @ w_out^T + b_out  [4096, 1024]
    sgemm_nt_bias<<<dim3(HID / 128, M_TOT / 128), blk>>>(
        att_buf, w_out, b_out, out, M_TOT, HID, HID);
}

// round 3
// speedup vs baseline: 1.2465x; 1.2465x over previous
#include <cuda_runtime.h>
#include <cuda_bf16.h>
#include <cstdint>
#include <math.h>

#define HID 1024
#define NHEAD 16
#define HDIM 64
#define BATCH 2
#define SEQ 2048
#define M_TOT (BATCH * SEQ)     // 4096
#define N_QKV (3 * HID)         // 3072
#define K3 (3 * HID)            // augmented K for bf16x3 split (=3072)

// ---------------------------------------------------------------------------
// Scratch (allocation-free rule: __device__ globals)
// ---------------------------------------------------------------------------
__device__ float g_qkv[(size_t)M_TOT * N_QKV];              // 48 MB
__device__ float g_att[(size_t)M_TOT * HID];                // 16 MB
__device__ __nv_bfloat16 g_xs[(size_t)M_TOT * K3];          // 24 MB
__device__ __nv_bfloat16 g_wqkvs[(size_t)N_QKV * K3];       // 18 MB
__device__ __nv_bfloat16 g_atts[(size_t)M_TOT * K3];        // 24 MB
__device__ __nv_bfloat16 g_wouts[(size_t)HID * K3];         // 6 MB

// ---------------------------------------------------------------------------
// Split fp32 -> bf16 hi/lo augmented matrix.
// mode 0 (A side): [hi | hi | lo]   mode 1 (B side): [hi | lo | hi]
// in: [R, K] fp32 row-major, out: [R, 3K] bf16 row-major
// ---------------------------------------------------------------------------
__global__ void __launch_bounds__(256) split_bf16(
    const float* __restrict__ in, __nv_bfloat16* __restrict__ out,
    int R, int K, int mode)
{
    const int half = K >> 1;
    const int total = R * half;
    for (int i = blockIdx.x * blockDim.x + threadIdx.x; i < total;
         i += gridDim.x * blockDim.x) {
        int r = i / half;
        int k2 = (i - r * half) * 2;
        float2 x = *(const float2*)(in + (size_t)r * K + k2);
        __nv_bfloat16 h0 = __float2bfloat16(x.x);
        __nv_bfloat16 h1 = __float2bfloat16(x.y);
        __nv_bfloat16 l0 = __float2bfloat16(x.x - __bfloat162float(h0));
        __nv_bfloat16 l1 = __float2bfloat16(x.y - __bfloat162float(h1));
        __nv_bfloat162 hh, ll;
        hh.x = h0; hh.y = h1;
        ll.x = l0; ll.y = l1;
        __nv_bfloat162* o = (__nv_bfloat162*)(out + (size_t)r * (3 * K) + k2);
        const int KH = K >> 1;  // in bf16x2 units
        if (mode == 0) {
            o[0] = hh; o[KH] = hh; o[2 * KH] = ll;
        } else {
            o[0] = hh; o[KH] = ll; o[2 * KH] = hh;
        }
    }
}

// ---------------------------------------------------------------------------
// HMMA helpers (sm_80-compatible PTX; works on plain sm_103 target)
// ---------------------------------------------------------------------------
__device__ __forceinline__ uint32_t smem_u32(const void* p) {
    uint32_t a;
    asm("{ .reg .u64 t; cvta.to.shared.u64 t, %1; cvt.u32.u64 %0, t; }"
        : "=r"(a) : "l"(p));
    return a;
}

__device__ __forceinline__ void cp16(uint32_t dst, const void* src) {
    asm volatile("cp.async.cg.shared.global [%0], [%1], 16;"
                 :: "r"(dst), "l"(src));
}
__device__ __forceinline__ void cp_commit() {
    asm volatile("cp.async.commit_group;");
}
template <int N>
__device__ __forceinline__ void cp_wait() {
    asm volatile("cp.async.wait_group %0;" :: "n"(N));
}

__device__ __forceinline__ void ldm_x4(uint32_t addr, uint32_t& r0, uint32_t& r1,
                                       uint32_t& r2, uint32_t& r3) {
    asm volatile("ldmatrix.sync.aligned.m8n8.x4.shared.b16 {%0,%1,%2,%3}, [%4];"
                 : "=r"(r0), "=r"(r1), "=r"(r2), "=r"(r3) : "r"(addr));
}

__device__ __forceinline__ void mma_bf16(float* c, const uint32_t* a,
                                         uint32_t b0, uint32_t b1) {
    asm volatile(
        "mma.sync.aligned.m16n8k16.row.col.f32.bf16.bf16.f32 "
        "{%0,%1,%2,%3}, {%4,%5,%6,%7}, {%8,%9}, {%0,%1,%2,%3};"
        : "+f"(c[0]), "+f"(c[1]), "+f"(c[2]), "+f"(c[3])
        : "r"(a[0]), "r"(a[1]), "r"(a[2]), "r"(a[3]), "r"(b0), "r"(b1));
}

// ---------------------------------------------------------------------------
// HMMA bf16 NT GEMM: C[M,N] = A[M,K]@B[N,K]^T + bias[N], fp32 accum.
// 128x128 CTA tile, BK=32, cp.async double-buffered, 8 warps @ 64x32 each.
// smem rows padded to 40 bf16 (80B) -> conflict-free ldmatrix.
// ---------------------------------------------------------------------------
#define GBM 128
#define GBN 128
#define GBK 32
#define LDS 40                      // smem row pitch in bf16 elems

__global__ void __launch_bounds__(256) gemm_hmma(
    const __nv_bfloat16* __restrict__ A, const __nv_bfloat16* __restrict__ B,
    const float* __restrict__ bias, float* __restrict__ C,
    int M, int N, int K)
{
    __shared__ __nv_bfloat16 sA[2][GBM * LDS];
    __shared__ __nv_bfloat16 sB[2][GBN * LDS];

    const int tid = threadIdx.x;
    const int wid = tid >> 5;
    const int lane = tid & 31;
    const int warp_m = (wid & 1) * 64;     // 0 or 64
    const int warp_n = (wid >> 1) * 32;    // 0,32,64,96
    const int m0 = blockIdx.y * GBM;
    const int n0 = blockIdx.x * GBN;

    const uint32_t sA0 = smem_u32(&sA[0][0]);
    const uint32_t sB0 = smem_u32(&sB[0][0]);
    const uint32_t stageA = GBM * LDS * 2;  // bytes per A stage
    const uint32_t stageB = GBN * LDS * 2;

    // cp.async mapping: idx in [0,512): row=idx>>2, chunk c=idx&3 (16B each)
    const int ld_row = tid >> 2;       // with t offset below
    const int ld_c = tid & 3;

    float acc[4][4][4];
#pragma unroll
    for (int i = 0; i < 4; i++)
#pragma unroll
        for (int j = 0; j < 4; j++)
#pragma unroll
            for (int q = 0; q < 4; q++) acc[i][j][q] = 0.f;

    const int NS = K / GBK;

    // --- stage loader ---
    auto load_stage = [&](int s, int p) {
        const int k0 = s * GBK;
#pragma unroll
        for (int t = 0; t < 2; t++) {
            int row = ld_row + t * 64;
            uint32_t doff = (uint32_t)(row * LDS * 2 + ld_c * 16);
            cp16(sA0 + p * stageA + doff,
                 A + (size_t)(m0 + row) * K + k0 + ld_c * 8);
            cp16(sB0 + p * stageB + doff,
                 B + (size_t)(n0 + row) * K + k0 + ld_c * 8);
        }
        cp_commit();
    };

    load_stage(0, 0);

    // ldmatrix base offsets (bf16 elems)
    const int a_row = warp_m + (lane & 15);
    const int b_row = warp_n + (lane & 15);
    const int k_half = (lane >> 4) * 8;

    for (int s = 0; s < NS; s++) {
        const int p = s & 1;
        if (s + 1 < NS) load_stage(s + 1, p ^ 1);
        if (s + 1 < NS) cp_wait<1>(); else cp_wait<0>();
        __syncthreads();

        const uint32_t aBase = sA0 + p * stageA;
        const uint32_t bBase = sB0 + p * stageB;

#pragma unroll
        for (int kk = 0; kk < 2; kk++) {
            const int kc = kk * 16 + k_half;
            uint32_t af[4][4];
#pragma unroll
            for (int i = 0; i < 4; i++) {
                uint32_t addr = aBase + (uint32_t)(((a_row + i * 16) * LDS + kc) * 2);
                ldm_x4(addr, af[i][0], af[i][1], af[i][2], af[i][3]);
            }
            uint32_t bf[4][2];
#pragma unroll
            for (int jp = 0; jp < 2; jp++) {
                uint32_t addr = bBase + (uint32_t)(((b_row + jp * 16) * LDS + kc) * 2);
                uint32_t r0, r1, r2, r3;
                ldm_x4(addr, r0, r1, r2, r3);
                // matrices: m0=(n0-7,k0-7) m1=(n8-15,k0-7) m2=(n0-7,k8-15) m3=(n8-15,k8-15)
                bf[jp * 2 + 0][0] = r0; bf[jp * 2 + 0][1] = r2;
                bf[jp * 2 + 1][0] = r1; bf[jp * 2 + 1][1] = r3;
            }
#pragma unroll
            for (int i = 0; i < 4; i++)
#pragma unroll
                for (int j = 0; j < 4; j++)
                    mma_bf16(acc[i][j], af[i], bf[j][0], bf[j][1]);
        }
        __syncthreads();
    }

    // Epilogue: C layout per mma fragment
    const int row_g = lane >> 2;
    const int col_g = (lane & 3) * 2;
#pragma unroll
    for (int i = 0; i < 4; i++) {
#pragma unroll
        for (int j = 0; j < 4; j++) {
            int row = m0 + warp_m + i * 16 + row_g;
            int col = n0 + warp_n + j * 8 + col_g;
            float b0 = bias[col], b1 = bias[col + 1];
            float2 v0 = make_float2(acc[i][j][0] + b0, acc[i][j][1] + b1);
            float2 v1 = make_float2(acc[i][j][2] + b0, acc[i][j][3] + b1);
            *(float2*)(C + (size_t)row * N + col) = v0;
            *(float2*)(C + (size_t)(row + 8) * N + col) = v1;
        }
    }
}

// ---------------------------------------------------------------------------
// Flash attention, fp32 (unchanged, measured ~1030us). CTA = (b,h,64 q-rows).
// ---------------------------------------------------------------------------
#define PAD 68

__global__ void __launch_bounds__(256) attn_kernel(
    const float* __restrict__ qkv, float* __restrict__ out)
{
    extern __shared__ float sm[];
    float (*Qs)[PAD] = (float(*)[PAD])(sm);
    float (*Ks)[PAD] = (float(*)[PAD])(sm + 64 * PAD);
    float (*Vs)[PAD] = (float(*)[PAD])(sm + 2 * 64 * PAD);
    float (*Ps)[PAD] = (float(*)[PAD])(sm + 3 * 64 * PAD);

    const int tid = threadIdx.x;
    const int tx = tid & 15;
    const int ty = tid >> 4;
    const int bh = blockIdx.y;
    const int b = bh >> 4, h = bh & 15;
    const int q0 = blockIdx.x * 64;
    const float scale = 0.125f;

    const float* base = qkv + (size_t)b * SEQ * N_QKV + h * HDIM;
    const float* Qg = base;
    const float* Kg = base + HID;
    const float* Vg = base + 2 * HID;

#pragma unroll
    for (int p = 0; p < 4; p++) {
        int idx = tid + p * 256;
        int i  = idx >> 4;
        int d4 = (idx & 15) << 2;
        float4 v = *(const float4*)(Qg + (size_t)(q0 + i) * N_QKV + d4);
        Qs[d4 + 0][i] = v.x * scale;
        Qs[d4 + 1][i] = v.y * scale;
        Qs[d4 + 2][i] = v.z * scale;
        Qs[d4 + 3][i] = v.w * scale;
    }

    float m[4], l[4], o[4][4];
#pragma unroll
    for (int ii = 0; ii < 4; ii++) {
        m[ii] = -1e30f;
        l[ii] = 0.f;
#pragma unroll
        for (int jj = 0; jj < 4; jj++) o[ii][jj] = 0.f;
    }

    for (int kt = 0; kt < SEQ / 64; kt++) {
        __syncthreads();
        const int j0 = kt * 64;
#pragma unroll
        for (int p = 0; p < 4; p++) {
            int idx = tid + p * 256;
            int j  = idx >> 4;
            int d4 = (idx & 15) << 2;
            float4 v = *(const float4*)(Kg + (size_t)(j0 + j) * N_QKV + d4);
            Ks[d4 + 0][j] = v.x;
            Ks[d4 + 1][j] = v.y;
            Ks[d4 + 2][j] = v.z;
            Ks[d4 + 3][j] = v.w;
            float4 w = *(const float4*)(Vg + (size_t)(j0 + j) * N_QKV + d4);
            *(float4*)&Vs[j][d4] = w;
        }
        __syncthreads();

        float s[4][4];
#pragma unroll
        for (int ii = 0; ii < 4; ii++)
#pragma unroll
            for (int jj = 0; jj < 4; jj++) s[ii][jj] = 0.f;

#pragma unroll
        for (int d = 0; d < 64; d++) {
            float qa[4], kb[4];
            *(float4*)qa = *(const float4*)&Qs[d][ty * 4];
            *(float4*)kb = *(const float4*)&Ks[d][tx * 4];
#pragma unroll
            for (int ii = 0; ii < 4; ii++)
#pragma unroll
                for (int jj = 0; jj < 4; jj++)
                    s[ii][jj] += qa[ii] * kb[jj];
        }

#pragma unroll
        for (int ii = 0; ii < 4; ii++) {
            float tmax = fmaxf(fmaxf(s[ii][0], s[ii][1]), fmaxf(s[ii][2], s[ii][3]));
#pragma unroll
            for (int off = 8; off; off >>= 1)
                tmax = fmaxf(tmax, __shfl_xor_sync(0xffffffffu, tmax, off));
            float mn = fmaxf(m[ii], tmax);
            float alpha = __expf(m[ii] - mn);
            m[ii] = mn;
            float rs = 0.f;
#pragma unroll
            for (int jj = 0; jj < 4; jj++) {
                float pij = __expf(s[ii][jj] - mn);
                s[ii][jj] = pij;
                rs += pij;
            }
#pragma unroll
            for (int off = 8; off; off >>= 1)
                rs += __shfl_xor_sync(0xffffffffu, rs, off);
            l[ii] = l[ii] * alpha + rs;
#pragma unroll
            for (int jj = 0; jj < 4; jj++) o[ii][jj] *= alpha;
#pragma unroll
            for (int jj = 0; jj < 4; jj++)
                Ps[tx * 4 + jj][ty * 4 + ii] = s[ii][jj];
        }
        __syncthreads();

#pragma unroll
        for (int j = 0; j < 64; j++) {
            float pa[4], vb[4];
            *(float4*)pa = *(const float4*)&Ps[j][ty * 4];
            *(float4*)vb = *(const float4*)&Vs[j][tx * 4];
#pragma unroll
            for (int ii = 0; ii < 4; ii++)
#pragma unroll
                for (int jj = 0; jj < 4; jj++)
                    o[ii][jj] += pa[ii] * vb[jj];
        }
    }

#pragma unroll
    for (int ii = 0; ii < 4; ii++) {
        float inv = 1.f / l[ii];
        int row = q0 + ty * 4 + ii;
        float* op = out + ((size_t)(b * SEQ + row)) * HID + h * HDIM + tx * 4;
        float4 r = make_float4(o[ii][0] * inv, o[ii][1] * inv,
                               o[ii][2] * inv, o[ii][3] * inv);
        *(float4*)op = r;
    }
}

// ---------------------------------------------------------------------------
// Launch
// ---------------------------------------------------------------------------
extern "C" void kernel_launch(void* const* d_in, const int* in_sizes, int n_in,
                              void* d_out, int out_size)
{
    const float *x = nullptr, *w_qkv = nullptr, *b_qkv = nullptr,
                *w_out = nullptr, *b_out = nullptr;
    for (int i = 0; i < n_in; i++) {
        const float* p = (const float*)d_in[i];
        switch (in_sizes[i]) {
            case M_TOT * HID: x = p; break;
            case N_QKV * HID: w_qkv = p; break;
            case N_QKV:       b_qkv = p; break;
            case HID * HID:   w_out = p; break;
            case HID:         b_out = p; break;
        }
    }
    float* out = (float*)d_out;

    float *qkv_buf, *att_buf;
    __nv_bfloat16 *xs, *wqkvs, *atts, *wouts;
    cudaGetSymbolAddress((void**)&qkv_buf, g_qkv);
    cudaGetSymbolAddress((void**)&att_buf, g_att);
    cudaGetSymbolAddress((void**)&xs, g_xs);
    cudaGetSymbolAddress((void**)&wqkvs, g_wqkvs);
    cudaGetSymbolAddress((void**)&atts, g_atts);
    cudaGetSymbolAddress((void**)&wouts, g_wouts);

    const int attn_smem = 4 * 64 * PAD * (int)sizeof(float);
    cudaFuncSetAttribute(attn_kernel,
                         cudaFuncAttributeMaxDynamicSharedMemorySize, attn_smem);

    dim3 blk(256);

    // Split inputs into bf16x3 augmented matrices
    split_bf16<<<1024, blk>>>(x,     xs,    M_TOT, HID, 0);
    split_bf16<<<1024, blk>>>(w_qkv, wqkvs, N_QKV, HID, 1);

    // GEMM1: qkv = x @ w_qkv^T + b_qkv   [4096, 3072], K'=3072
    gemm_hmma<<<dim3(N_QKV / GBN, M_TOT / GBM), blk>>>(
        xs, wqkvs, b_qkv, qkv_buf, M_TOT, N_QKV, K3);

    // Attention
    attn_kernel<<<dim3(SEQ / 64, BATCH * NHEAD), blk, attn_smem>>>(qkv_buf, att_buf);

    // Split attention output + w_out
    split_bf16<<<1024, blk>>>(att_buf, atts,  M_TOT, HID, 0);
    split_bf16<<<1024, blk>>>(w_out,   wouts, HID,   HID, 1);

    // GEMM2: out = att @ w_out^T + b_out  [4096, 1024], K'=3072
    gemm_hmma<<<dim3(HID / GBN, M_TOT / GBM), blk>>>(
        atts, wouts, b_out, out, M_TOT, HID, K3);
}

// round 4
// speedup vs baseline: 2.2634x; 1.8157x over previous
#include <cuda_runtime.h>
#include <cuda_bf16.h>
#include <cstdint>
#include <math.h>

#define HID 1024
#define NHEAD 16
#define HDIM 64
#define BATCH 2
#define SEQ 2048
#define M_TOT (BATCH * SEQ)     // 4096
#define N_QKV (3 * HID)         // 3072
#define K3 (3 * HID)            // augmented K for bf16x3 split

// ---------------------------------------------------------------------------
// Scratch
// ---------------------------------------------------------------------------
__device__ __nv_bfloat16 g_qkvh[(size_t)M_TOT * N_QKV];     // 24 MB
__device__ __nv_bfloat16 g_qkvl[(size_t)M_TOT * N_QKV];     // 24 MB
__device__ __nv_bfloat16 g_xs[(size_t)M_TOT * K3];          // 24 MB
__device__ __nv_bfloat16 g_wqkvs[(size_t)N_QKV * K3];       // 18 MB
__device__ __nv_bfloat16 g_atts[(size_t)M_TOT * K3];        // 24 MB
__device__ __nv_bfloat16 g_wouts[(size_t)HID * K3];         // 6 MB

// ---------------------------------------------------------------------------
// Helpers
// ---------------------------------------------------------------------------
__device__ __forceinline__ uint32_t smem_u32(const void* p) {
    uint32_t a;
    asm("{ .reg .u64 t; cvta.to.shared.u64 t, %1; cvt.u32.u64 %0, t; }"
        : "=r"(a) : "l"(p));
    return a;
}
__device__ __forceinline__ void cp16(uint32_t dst, const void* src) {
    asm volatile("cp.async.cg.shared.global [%0], [%1], 16;" :: "r"(dst), "l"(src));
}
__device__ __forceinline__ void cp_commit() { asm volatile("cp.async.commit_group;"); }
template <int N>
__device__ __forceinline__ void cp_wait() { asm volatile("cp.async.wait_group %0;" :: "n"(N)); }

__device__ __forceinline__ void ldm_x4(uint32_t addr, uint32_t& r0, uint32_t& r1,
                                       uint32_t& r2, uint32_t& r3) {
    asm volatile("ldmatrix.sync.aligned.m8n8.x4.shared.b16 {%0,%1,%2,%3}, [%4];"
                 : "=r"(r0), "=r"(r1), "=r"(r2), "=r"(r3) : "r"(addr));
}
__device__ __forceinline__ void ldm_x4_t(uint32_t addr, uint32_t& r0, uint32_t& r1,
                                         uint32_t& r2, uint32_t& r3) {
    asm volatile("ldmatrix.sync.aligned.m8n8.x4.trans.shared.b16 {%0,%1,%2,%3}, [%4];"
                 : "=r"(r0), "=r"(r1), "=r"(r2), "=r"(r3) : "r"(addr));
}
__device__ __forceinline__ void mma_bf16(float* c, const uint32_t* a,
                                         uint32_t b0, uint32_t b1) {
    asm volatile(
        "mma.sync.aligned.m16n8k16.row.col.f32.bf16.bf16.f32 "
        "{%0,%1,%2,%3}, {%4,%5,%6,%7}, {%8,%9}, {%0,%1,%2,%3};"
        : "+f"(c[0]), "+f"(c[1]), "+f"(c[2]), "+f"(c[3])
        : "r"(a[0]), "r"(a[1]), "r"(a[2]), "r"(a[3]), "r"(b0), "r"(b1));
}
__device__ __forceinline__ uint32_t packbf(float a, float b) {
    __nv_bfloat162 t = __floats2bfloat162_rn(a, b);
    return *(uint32_t*)&t;
}

// ---------------------------------------------------------------------------
// Split fp32 -> bf16 hi/lo augmented. mode0: [hi|hi|lo], mode1: [hi|lo|hi]
// ---------------------------------------------------------------------------
__global__ void __launch_bounds__(256) split_bf16(
    const float* __restrict__ in, __nv_bfloat16* __restrict__ out,
    int R, int K, int mode)
{
    const int half = K >> 1;
    const int total = R * half;
    for (int i = blockIdx.x * blockDim.x + threadIdx.x; i < total;
         i += gridDim.x * blockDim.x) {
        int r = i / half;
        int k2 = (i - r * half) * 2;
        float2 x = *(const float2*)(in + (size_t)r * K + k2);
        __nv_bfloat16 h0 = __float2bfloat16(x.x);
        __nv_bfloat16 h1 = __float2bfloat16(x.y);
        __nv_bfloat16 l0 = __float2bfloat16(x.x - __bfloat162float(h0));
        __nv_bfloat16 l1 = __float2bfloat16(x.y - __bfloat162float(h1));
        __nv_bfloat162 hh, ll;
        hh.x = h0; hh.y = h1;
        ll.x = l0; ll.y = l1;
        __nv_bfloat162* o = (__nv_bfloat162*)(out + (size_t)r * (3 * K) + k2);
        const int KH = K >> 1;
        if (mode == 0) { o[0] = hh; o[KH] = hh; o[2 * KH] = ll; }
        else           { o[0] = hh; o[KH] = ll; o[2 * KH] = hh; }
    }
}

// ---------------------------------------------------------------------------
// HMMA bf16 NT GEMM mainloop (128x128 tile, BK=32, double-buffered cp.async).
// Epilogue selected by template: fp32 C, or bf16 hi/lo pair.
// ---------------------------------------------------------------------------
#define GBM 128
#define GBN 128
#define GBK 32
#define LDS 40

template <bool BF16OUT>
__global__ void __launch_bounds__(256) gemm_hmma(
    const __nv_bfloat16* __restrict__ A, const __nv_bfloat16* __restrict__ B,
    const float* __restrict__ bias, float* __restrict__ C,
    __nv_bfloat16* __restrict__ Ch, __nv_bfloat16* __restrict__ Cl,
    int M, int N, int K)
{
    __shared__ __nv_bfloat16 sA[2][GBM * LDS];
    __shared__ __nv_bfloat16 sB[2][GBN * LDS];

    const int tid = threadIdx.x;
    const int wid = tid >> 5;
    const int lane = tid & 31;
    const int warp_m = (wid & 1) * 64;
    const int warp_n = (wid >> 1) * 32;
    const int m0 = blockIdx.y * GBM;
    const int n0 = blockIdx.x * GBN;

    const uint32_t sA0 = smem_u32(&sA[0][0]);
    const uint32_t sB0 = smem_u32(&sB[0][0]);
    const uint32_t stageA = GBM * LDS * 2;
    const uint32_t stageB = GBN * LDS * 2;

    const int ld_row = tid >> 2;
    const int ld_c = tid & 3;

    float acc[4][4][4];
#pragma unroll
    for (int i = 0; i < 4; i++)
#pragma unroll
        for (int j = 0; j < 4; j++)
#pragma unroll
            for (int q = 0; q < 4; q++) acc[i][j][q] = 0.f;

    const int NS = K / GBK;

    auto load_stage = [&](int s, int p) {
        const int k0 = s * GBK;
#pragma unroll
        for (int t = 0; t < 2; t++) {
            int row = ld_row + t * 64;
            uint32_t doff = (uint32_t)(row * LDS * 2 + ld_c * 16);
            cp16(sA0 + p * stageA + doff, A + (size_t)(m0 + row) * K + k0 + ld_c * 8);
            cp16(sB0 + p * stageB + doff, B + (size_t)(n0 + row) * K + k0 + ld_c * 8);
        }
        cp_commit();
    };

    load_stage(0, 0);

    const int a_row = warp_m + (lane & 15);
    const int b_row = warp_n + (lane & 15);
    const int k_half = (lane >> 4) * 8;

    for (int s = 0; s < NS; s++) {
        const int p = s & 1;
        if (s + 1 < NS) load_stage(s + 1, p ^ 1);
        if (s + 1 < NS) cp_wait<1>(); else cp_wait<0>();
        __syncthreads();

        const uint32_t aBase = sA0 + p * stageA;
        const uint32_t bBase = sB0 + p * stageB;

#pragma unroll
        for (int kk = 0; kk < 2; kk++) {
            const int kc = kk * 16 + k_half;
            uint32_t af[4][4];
#pragma unroll
            for (int i = 0; i < 4; i++) {
                uint32_t addr = aBase + (uint32_t)(((a_row + i * 16) * LDS + kc) * 2);
                ldm_x4(addr, af[i][0], af[i][1], af[i][2], af[i][3]);
            }
            uint32_t bf[4][2];
#pragma unroll
            for (int jp = 0; jp < 2; jp++) {
                uint32_t addr = bBase + (uint32_t)(((b_row + jp * 16) * LDS + kc) * 2);
                uint32_t r0, r1, r2, r3;
                ldm_x4(addr, r0, r1, r2, r3);
                bf[jp * 2 + 0][0] = r0; bf[jp * 2 + 0][1] = r2;
                bf[jp * 2 + 1][0] = r1; bf[jp * 2 + 1][1] = r3;
            }
#pragma unroll
            for (int i = 0; i < 4; i++)
#pragma unroll
                for (int j = 0; j < 4; j++)
                    mma_bf16(acc[i][j], af[i], bf[j][0], bf[j][1]);
        }
        __syncthreads();
    }

    const int row_g = lane >> 2;
    const int col_g = (lane & 3) * 2;
#pragma unroll
    for (int i = 0; i < 4; i++) {
#pragma unroll
        for (int j = 0; j < 4; j++) {
            int row = m0 + warp_m + i * 16 + row_g;
            int col = n0 + warp_n + j * 8 + col_g;
            float b0 = bias[col], b1 = bias[col + 1];
            float v00 = acc[i][j][0] + b0, v01 = acc[i][j][1] + b1;
            float v10 = acc[i][j][2] + b0, v11 = acc[i][j][3] + b1;
            if (BF16OUT) {
                __nv_bfloat162 h0 = __floats2bfloat162_rn(v00, v01);
                __nv_bfloat162 h1 = __floats2bfloat162_rn(v10, v11);
                __nv_bfloat162 l0 = __floats2bfloat162_rn(
                    v00 - __bfloat162float(h0.x), v01 - __bfloat162float(h0.y));
                __nv_bfloat162 l1 = __floats2bfloat162_rn(
                    v10 - __bfloat162float(h1.x), v11 - __bfloat162float(h1.y));
                *(__nv_bfloat162*)(Ch + (size_t)row * N + col) = h0;
                *(__nv_bfloat162*)(Ch + (size_t)(row + 8) * N + col) = h1;
                *(__nv_bfloat162*)(Cl + (size_t)row * N + col) = l0;
                *(__nv_bfloat162*)(Cl + (size_t)(row + 8) * N + col) = l1;
            } else {
                *(float2*)(C + (size_t)row * N + col) = make_float2(v00, v01);
                *(float2*)(C + (size_t)(row + 8) * N + col) = make_float2(v10, v11);
            }
        }
    }
}

// ---------------------------------------------------------------------------
// Tensor-core flash attention, bf16x3 split, fp32 accumulate.
// CTA = 64 q-rows x (b,h); 4 warps x 16 rows; 64-key tiles.
// Writes GEMM2's augmented A matrix [hi|hi|lo] directly.
// ---------------------------------------------------------------------------
#define APITCH 72
#define ATT_SMEM (6 * 64 * APITCH * 2)   // 55296 B

__global__ void __launch_bounds__(128) attn_tc(
    const __nv_bfloat16* __restrict__ qh, const __nv_bfloat16* __restrict__ ql,
    __nv_bfloat16* __restrict__ atts)
{
    extern __shared__ __nv_bfloat16 sm[];
    __nv_bfloat16* Qh = sm;
    __nv_bfloat16* Ql = Qh + 64 * APITCH;
    __nv_bfloat16* Kh = Ql + 64 * APITCH;
    __nv_bfloat16* Kl = Kh + 64 * APITCH;
    __nv_bfloat16* Vh = Kl + 64 * APITCH;
    __nv_bfloat16* Vl = Vh + 64 * APITCH;

    const int tid = threadIdx.x;
    const int wid = tid >> 5;
    const int lane = tid & 31;
    const int bh = blockIdx.y;
    const int b = bh >> 4, h = bh & 15;
    const int q0 = blockIdx.x * 64;
    const size_t tokbase = (size_t)b * SEQ;

    // Load Q tile (hi, lo): rows [q0, q0+64), cols h*64..+64
    {
        const size_t qoff = (tokbase + q0) * N_QKV + h * HDIM;
#pragma unroll
        for (int t = 0; t < 4; t++) {
            int idx = tid + t * 128;      // 0..511
            int row = idx >> 3;
            int ch = (idx & 7) * 8;
            *(uint4*)(Qh + row * APITCH + ch) = *(const uint4*)(qh + qoff + (size_t)row * N_QKV + ch);
            *(uint4*)(Ql + row * APITCH + ch) = *(const uint4*)(ql + qoff + (size_t)row * N_QKV + ch);
        }
    }

    const uint32_t sQh = smem_u32(Qh), sQl = smem_u32(Ql);
    const uint32_t sKh = smem_u32(Kh), sKl = smem_u32(Kl);
    const uint32_t sVh = smem_u32(Vh), sVl = smem_u32(Vl);

    const int lrow = lane & 15;
    const int lkh = (lane >> 4) * 8;
    // trans-ldmatrix lane mapping for V
    const int vkey = (lane >> 4) * 8 + (lane & 7);
    const int vd = ((lane >> 3) & 1) * 8;

    float m0 = -1e30f, m1 = -1e30f, l0 = 0.f, l1 = 0.f;
    float o[8][4];
#pragma unroll
    for (int t = 0; t < 8; t++)
#pragma unroll
        for (int q = 0; q < 4; q++) o[t][q] = 0.f;

    for (int kt = 0; kt < SEQ / 64; kt++) {
        __syncthreads();
        // Load K/V (hi, lo) tiles: keys [kt*64, +64)
        {
            const size_t koff = (tokbase + kt * 64) * N_QKV + HID + h * HDIM;
            const size_t voff = koff + HID;
#pragma unroll
            for (int t = 0; t < 4; t++) {
                int idx = tid + t * 128;
                int row = idx >> 3;
                int ch = (idx & 7) * 8;
                size_t g = (size_t)row * N_QKV + ch;
                *(uint4*)(Kh + row * APITCH + ch) = *(const uint4*)(qh + koff + g);
                *(uint4*)(Kl + row * APITCH + ch) = *(const uint4*)(ql + koff + g);
                *(uint4*)(Vh + row * APITCH + ch) = *(const uint4*)(qh + voff + g);
                *(uint4*)(Vl + row * APITCH + ch) = *(const uint4*)(ql + voff + g);
            }
        }
        __syncthreads();

        // ---- S = Q K^T (3-term split) ----
        float sf[8][4];
#pragma unroll
        for (int t = 0; t < 8; t++)
#pragma unroll
            for (int q = 0; q < 4; q++) sf[t][q] = 0.f;

#pragma unroll
        for (int kk = 0; kk < 4; kk++) {
            const uint32_t qoff2 = (uint32_t)(((wid * 16 + lrow) * APITCH + kk * 16 + lkh) * 2);
            uint32_t ah[4], al[4];
            ldm_x4(sQh + qoff2, ah[0], ah[1], ah[2], ah[3]);
            ldm_x4(sQl + qoff2, al[0], al[1], al[2], al[3]);
#pragma unroll
            for (int jp = 0; jp < 4; jp++) {
                const uint32_t koff2 = (uint32_t)(((jp * 16 + lrow) * APITCH + kk * 16 + lkh) * 2);
                uint32_t h0, h1, h2, h3, e0, e1, e2, e3;
                ldm_x4(sKh + koff2, h0, h1, h2, h3);
                ldm_x4(sKl + koff2, e0, e1, e2, e3);
                // n-tile 2jp: b = {r0, r2}; n-tile 2jp+1: {r1, r3}
                mma_bf16(sf[2 * jp],     ah, h0, h2);
                mma_bf16(sf[2 * jp],     ah, e0, e2);
                mma_bf16(sf[2 * jp],     al, h0, h2);
                mma_bf16(sf[2 * jp + 1], ah, h1, h3);
                mma_bf16(sf[2 * jp + 1], ah, e1, e3);
                mma_bf16(sf[2 * jp + 1], al, h1, h3);
            }
        }

        // ---- online softmax ----
        float tm0 = -1e30f, tm1 = -1e30f;
#pragma unroll
        for (int t = 0; t < 8; t++) {
#pragma unroll
            for (int q = 0; q < 4; q++) sf[t][q] *= 0.125f;
            tm0 = fmaxf(tm0, fmaxf(sf[t][0], sf[t][1]));
            tm1 = fmaxf(tm1, fmaxf(sf[t][2], sf[t][3]));
        }
        tm0 = fmaxf(tm0, __shfl_xor_sync(0xffffffffu, tm0, 1));
        tm0 = fmaxf(tm0, __shfl_xor_sync(0xffffffffu, tm0, 2));
        tm1 = fmaxf(tm1, __shfl_xor_sync(0xffffffffu, tm1, 1));
        tm1 = fmaxf(tm1, __shfl_xor_sync(0xffffffffu, tm1, 2));

        float mn0 = fmaxf(m0, tm0), mn1 = fmaxf(m1, tm1);
        float a0 = __expf(m0 - mn0), a1 = __expf(m1 - mn1);
        m0 = mn0; m1 = mn1;

        float rs0 = 0.f, rs1 = 0.f;
#pragma unroll
        for (int t = 0; t < 8; t++) {
            sf[t][0] = __expf(sf[t][0] - mn0);
            sf[t][1] = __expf(sf[t][1] - mn0);
            sf[t][2] = __expf(sf[t][2] - mn1);
            sf[t][3] = __expf(sf[t][3] - mn1);
            rs0 += sf[t][0] + sf[t][1];
            rs1 += sf[t][2] + sf[t][3];
        }
        rs0 += __shfl_xor_sync(0xffffffffu, rs0, 1);
        rs0 += __shfl_xor_sync(0xffffffffu, rs0, 2);
        rs1 += __shfl_xor_sync(0xffffffffu, rs1, 1);
        rs1 += __shfl_xor_sync(0xffffffffu, rs1, 2);
        l0 = l0 * a0 + rs0;
        l1 = l1 * a1 + rs1;

#pragma unroll
        for (int t = 0; t < 8; t++) {
            o[t][0] *= a0; o[t][1] *= a0;
            o[t][2] *= a1; o[t][3] *= a1;
        }

        // ---- pack P into A-operand frags (hi + lo) ----
        uint32_t ph[4][4], pl[4][4];
#pragma unroll
        for (int kk = 0; kk < 4; kk++) {
            float* c0 = sf[2 * kk];
            float* c1 = sf[2 * kk + 1];
            ph[kk][0] = packbf(c0[0], c0[1]);
            ph[kk][1] = packbf(c0[2], c0[3]);
            ph[kk][2] = packbf(c1[0], c1[1]);
            ph[kk][3] = packbf(c1[2], c1[3]);
            __nv_bfloat162* hp;
            hp = (__nv_bfloat162*)&ph[kk][0];
            pl[kk][0] = packbf(c0[0] - __bfloat162float(hp->x), c0[1] - __bfloat162float(hp->y));
            hp = (__nv_bfloat162*)&ph[kk][1];
            pl[kk][1] = packbf(c0[2] - __bfloat162float(hp->x), c0[3] - __bfloat162float(hp->y));
            hp = (__nv_bfloat162*)&ph[kk][2];
            pl[kk][2] = packbf(c1[0] - __bfloat162float(hp->x), c1[1] - __bfloat162float(hp->y));
            hp = (__nv_bfloat162*)&ph[kk][3];
            pl[kk][3] = packbf(c1[2] - __bfloat162float(hp->x), c1[3] - __bfloat162float(hp->y));
        }

        // ---- O += P V (3-term split), V via ldmatrix.trans ----
#pragma unroll
        for (int kk = 0; kk < 4; kk++) {
#pragma unroll
            for (int dt = 0; dt < 4; dt++) {
                const uint32_t voff2 = (uint32_t)(((kk * 16 + vkey) * APITCH + dt * 16 + vd) * 2);
                uint32_t h0, h1, h2, h3, e0, e1, e2, e3;
                ldm_x4_t(sVh + voff2, h0, h1, h2, h3);
                ldm_x4_t(sVl + voff2, e0, e1, e2, e3);
                mma_bf16(o[2 * dt],     ph[kk], h0, h2);
                mma_bf16(o[2 * dt],     ph[kk], e0, e2);
                mma_bf16(o[2 * dt],     pl[kk], h0, h2);
                mma_bf16(o[2 * dt + 1], ph[kk], h1, h3);
                mma_bf16(o[2 * dt + 1], ph[kk], e1, e3);
                mma_bf16(o[2 * dt + 1], pl[kk], h1, h3);
            }
        }
    }

    // ---- epilogue: write augmented [hi|hi|lo] rows for GEMM2 ----
    const float inv0 = 1.f / l0, inv1 = 1.f / l1;
    const int gr0 = q0 + wid * 16 + (lane >> 2);
    const int gr1 = gr0 + 8;
    const size_t r0base = (tokbase + gr0) * (size_t)K3;
    const size_t r1base = (tokbase + gr1) * (size_t)K3;
#pragma unroll
    for (int t = 0; t < 8; t++) {
        int col = h * HDIM + t * 8 + (lane & 3) * 2;
        float v00 = o[t][0] * inv0, v01 = o[t][1] * inv0;
        float v10 = o[t][2] * inv1, v11 = o[t][3] * inv1;
        __nv_bfloat162 h0 = __floats2bfloat162_rn(v00, v01);
        __nv_bfloat162 h1 = __floats2bfloat162_rn(v10, v11);
        __nv_bfloat162 lo0 = __floats2bfloat162_rn(v00 - __bfloat162float(h0.x),
                                                   v01 - __bfloat162float(h0.y));
        __nv_bfloat162 lo1 = __floats2bfloat162_rn(v10 - __bfloat162float(h1.x),
                                                   v11 - __bfloat162float(h1.y));
        *(__nv_bfloat162*)(atts + r0base + col) = h0;
        *(__nv_bfloat162*)(atts + r0base + HID + col) = h0;
        *(__nv_bfloat162*)(atts + r0base + 2 * HID + col) = lo0;
        *(__nv_bfloat162*)(atts + r1base + col) = h1;
        *(__nv_bfloat162*)(atts + r1base + HID + col) = h1;
        *(__nv_bfloat162*)(atts + r1base + 2 * HID + col) = lo1;
    }
}

// ---------------------------------------------------------------------------
// Launch
// ---------------------------------------------------------------------------
extern "C" void kernel_launch(void* const* d_in, const int* in_sizes, int n_in,
                              void* d_out, int out_size)
{
    const float *x = nullptr, *w_qkv = nullptr, *b_qkv = nullptr,
                *w_out = nullptr, *b_out = nullptr;
    for (int i = 0; i < n_in; i++) {
        const float* p = (const float*)d_in[i];
        switch (in_sizes[i]) {
            case M_TOT * HID: x = p; break;
            case N_QKV * HID: w_qkv = p; break;
            case N_QKV:       b_qkv = p; break;
            case HID * HID:   w_out = p; break;
            case HID:         b_out = p; break;
        }
    }
    float* out = (float*)d_out;

    __nv_bfloat16 *qkvh, *qkvl, *xs, *wqkvs, *atts, *wouts;
    cudaGetSymbolAddress((void**)&qkvh, g_qkvh);
    cudaGetSymbolAddress((void**)&qkvl, g_qkvl);
    cudaGetSymbolAddress((void**)&xs, g_xs);
    cudaGetSymbolAddress((void**)&wqkvs, g_wqkvs);
    cudaGetSymbolAddress((void**)&atts, g_atts);
    cudaGetSymbolAddress((void**)&wouts, g_wouts);

    cudaFuncSetAttribute(attn_tc,
                         cudaFuncAttributeMaxDynamicSharedMemorySize, ATT_SMEM);

    dim3 blk(256);

    // Splits
    split_bf16<<<1024, blk>>>(x,     xs,    M_TOT, HID, 0);
    split_bf16<<<1024, blk>>>(w_qkv, wqkvs, N_QKV, HID, 1);
    split_bf16<<<1024, blk>>>(w_out, wouts, HID,   HID, 1);

    // GEMM1: qkv (bf16 hi/lo) = x @ w_qkv^T + b_qkv
    gemm_hmma<true><<<dim3(N_QKV / GBN, M_TOT / GBM), blk>>>(
        xs, wqkvs, b_qkv, nullptr, qkvh, qkvl, M_TOT, N_QKV, K3);

    // Attention (tensor-core): writes augmented A for GEMM2
    attn_tc<<<dim3(SEQ / 64, BATCH * NHEAD), dim3(128), ATT_SMEM>>>(qkvh, qkvl, atts);

    // GEMM2: out = att @ w_out^T + b_out
    gemm_hmma<false><<<dim3(HID / GBN, M_TOT / GBM), blk>>>(
        atts, wouts, b_out, out, nullptr, nullptr, M_TOT, HID, K3);
}

// round 5
// speedup vs baseline: 2.3055x; 1.0186x over previous
#include <cuda_runtime.h>
#include <cuda_bf16.h>
#include <cstdint>
#include <math.h>

#define HID 1024
#define NHEAD 16
#define HDIM 64
#define BATCH 2
#define SEQ 2048
#define M_TOT (BATCH * SEQ)     // 4096
#define N_QKV (3 * HID)         // 3072
#define K3 (3 * HID)            // augmented K for bf16x3 split

// ---------------------------------------------------------------------------
// Scratch
// ---------------------------------------------------------------------------
__device__ __nv_bfloat16 g_qkvh[(size_t)M_TOT * N_QKV];     // 24 MB
__device__ __nv_bfloat16 g_qkvl[(size_t)M_TOT * N_QKV];     // 24 MB
__device__ __nv_bfloat16 g_xs[(size_t)M_TOT * K3];          // 24 MB
__device__ __nv_bfloat16 g_wqkvs[(size_t)N_QKV * K3];       // 18 MB
__device__ __nv_bfloat16 g_atts[(size_t)M_TOT * K3];        // 24 MB
__device__ __nv_bfloat16 g_wouts[(size_t)HID * K3];         // 6 MB

// ---------------------------------------------------------------------------
// Helpers
// ---------------------------------------------------------------------------
__device__ __forceinline__ uint32_t smem_u32(const void* p) {
    uint32_t a;
    asm("{ .reg .u64 t; cvta.to.shared.u64 t, %1; cvt.u32.u64 %0, t; }"
        : "=r"(a) : "l"(p));
    return a;
}
__device__ __forceinline__ void cp16(uint32_t dst, const void* src) {
    asm volatile("cp.async.cg.shared.global [%0], [%1], 16;" :: "r"(dst), "l"(src));
}
__device__ __forceinline__ void cp_commit() { asm volatile("cp.async.commit_group;"); }
template <int N>
__device__ __forceinline__ void cp_wait() { asm volatile("cp.async.wait_group %0;" :: "n"(N)); }

__device__ __forceinline__ void ldm_x4(uint32_t addr, uint32_t& r0, uint32_t& r1,
                                       uint32_t& r2, uint32_t& r3) {
    asm volatile("ldmatrix.sync.aligned.m8n8.x4.shared.b16 {%0,%1,%2,%3}, [%4];"
                 : "=r"(r0), "=r"(r1), "=r"(r2), "=r"(r3) : "r"(addr));
}
__device__ __forceinline__ void ldm_x4_t(uint32_t addr, uint32_t& r0, uint32_t& r1,
                                         uint32_t& r2, uint32_t& r3) {
    asm volatile("ldmatrix.sync.aligned.m8n8.x4.trans.shared.b16 {%0,%1,%2,%3}, [%4];"
                 : "=r"(r0), "=r"(r1), "=r"(r2), "=r"(r3) : "r"(addr));
}
__device__ __forceinline__ void mma_bf16(float* c, const uint32_t* a,
                                         uint32_t b0, uint32_t b1) {
    asm volatile(
        "mma.sync.aligned.m16n8k16.row.col.f32.bf16.bf16.f32 "
        "{%0,%1,%2,%3}, {%4,%5,%6,%7}, {%8,%9}, {%0,%1,%2,%3};"
        : "+f"(c[0]), "+f"(c[1]), "+f"(c[2]), "+f"(c[3])
        : "r"(a[0]), "r"(a[1]), "r"(a[2]), "r"(a[3]), "r"(b0), "r"(b1));
}
__device__ __forceinline__ uint32_t packbf(float a, float b) {
    __nv_bfloat162 t = __floats2bfloat162_rn(a, b);
    return *(uint32_t*)&t;
}

// ---------------------------------------------------------------------------
// Split fp32 -> bf16 hi/lo augmented. mode0: [hi|hi|lo], mode1: [hi|lo|hi]
// ---------------------------------------------------------------------------
__global__ void __launch_bounds__(256) split_bf16(
    const float* __restrict__ in, __nv_bfloat16* __restrict__ out,
    int R, int K, int mode)
{
    const int half = K >> 1;
    const int total = R * half;
    for (int i = blockIdx.x * blockDim.x + threadIdx.x; i < total;
         i += gridDim.x * blockDim.x) {
        int r = i / half;
        int k2 = (i - r * half) * 2;
        float2 x = *(const float2*)(in + (size_t)r * K + k2);
        __nv_bfloat16 h0 = __float2bfloat16(x.x);
        __nv_bfloat16 h1 = __float2bfloat16(x.y);
        __nv_bfloat16 l0 = __float2bfloat16(x.x - __bfloat162float(h0));
        __nv_bfloat16 l1 = __float2bfloat16(x.y - __bfloat162float(h1));
        __nv_bfloat162 hh, ll;
        hh.x = h0; hh.y = h1;
        ll.x = l0; ll.y = l1;
        __nv_bfloat162* o = (__nv_bfloat162*)(out + (size_t)r * (3 * K) + k2);
        const int KH = K >> 1;
        if (mode == 0) { o[0] = hh; o[KH] = hh; o[2 * KH] = ll; }
        else           { o[0] = hh; o[KH] = ll; o[2 * KH] = hh; }
    }
}

// ---------------------------------------------------------------------------
// HMMA bf16 NT GEMM: 128x128 tile, BK=32, 4-stage cp.async pipeline,
// single __syncthreads per iteration. Epilogue: fp32 or bf16 hi/lo pair.
// ---------------------------------------------------------------------------
#define GBM 128
#define GBN 128
#define GBK 32
#define LDS 40
#define GSTAGES 4
#define STG_A (GBM * LDS * 2)              // 10240 B
#define STG_PAIR (STG_A * 2)               // 20480 B
#define GEMM_SMEM (GSTAGES * STG_PAIR)     // 81920 B

template <bool BF16OUT>
__global__ void __launch_bounds__(256, 2) gemm_hmma(
    const __nv_bfloat16* __restrict__ A, const __nv_bfloat16* __restrict__ B,
    const float* __restrict__ bias, float* __restrict__ C,
    __nv_bfloat16* __restrict__ Ch, __nv_bfloat16* __restrict__ Cl,
    int M, int N, int K)
{
    extern __shared__ char gsm[];
    const uint32_t sbase = smem_u32(gsm);

    const int tid = threadIdx.x;
    const int wid = tid >> 5;
    const int lane = tid & 31;
    const int warp_m = (wid & 1) * 64;
    const int warp_n = (wid >> 1) * 32;
    const int m0 = blockIdx.y * GBM;
    const int n0 = blockIdx.x * GBN;

    const int ld_row = tid >> 2;
    const int ld_c = tid & 3;

    float acc[4][4][4];
#pragma unroll
    for (int i = 0; i < 4; i++)
#pragma unroll
        for (int j = 0; j < 4; j++)
#pragma unroll
            for (int q = 0; q < 4; q++) acc[i][j][q] = 0.f;

    const int NS = K / GBK;

    auto load_stage = [&](int s, int p) {
        const int k0 = s * GBK;
        const uint32_t base = sbase + (uint32_t)p * STG_PAIR;
#pragma unroll
        for (int t = 0; t < 2; t++) {
            int row = ld_row + t * 64;
            uint32_t doff = (uint32_t)(row * LDS * 2 + ld_c * 16);
            cp16(base + doff,         A + (size_t)(m0 + row) * K + k0 + ld_c * 8);
            cp16(base + STG_A + doff, B + (size_t)(n0 + row) * K + k0 + ld_c * 8);
        }
    };

    // Prologue: stages 0..GSTAGES-2
#pragma unroll
    for (int s = 0; s < GSTAGES - 1; s++) {
        if (s < NS) load_stage(s, s);
        cp_commit();
    }

    const int a_row = warp_m + (lane & 15);
    const int b_row = warp_n + (lane & 15);
    const int k_half = (lane >> 4) * 8;

    for (int s = 0; s < NS; s++) {
        const int p = s & (GSTAGES - 1);
        cp_wait<GSTAGES - 2>();
        __syncthreads();
        {
            int ns = s + GSTAGES - 1;
            if (ns < NS) load_stage(ns, ns & (GSTAGES - 1));
            cp_commit();
        }

        const uint32_t aBase = sbase + (uint32_t)p * STG_PAIR;
        const uint32_t bBase = aBase + STG_A;

#pragma unroll
        for (int kk = 0; kk < 2; kk++) {
            const int kc = kk * 16 + k_half;
            uint32_t af[4][4];
#pragma unroll
            for (int i = 0; i < 4; i++) {
                uint32_t addr = aBase + (uint32_t)(((a_row + i * 16) * LDS + kc) * 2);
                ldm_x4(addr, af[i][0], af[i][1], af[i][2], af[i][3]);
            }
            uint32_t bf[4][2];
#pragma unroll
            for (int jp = 0; jp < 2; jp++) {
                uint32_t addr = bBase + (uint32_t)(((b_row + jp * 16) * LDS + kc) * 2);
                uint32_t r0, r1, r2, r3;
                ldm_x4(addr, r0, r1, r2, r3);
                bf[jp * 2 + 0][0] = r0; bf[jp * 2 + 0][1] = r2;
                bf[jp * 2 + 1][0] = r1; bf[jp * 2 + 1][1] = r3;
            }
#pragma unroll
            for (int i = 0; i < 4; i++)
#pragma unroll
                for (int j = 0; j < 4; j++)
                    mma_bf16(acc[i][j], af[i], bf[j][0], bf[j][1]);
        }
    }

    const int row_g = lane >> 2;
    const int col_g = (lane & 3) * 2;
#pragma unroll
    for (int i = 0; i < 4; i++) {
#pragma unroll
        for (int j = 0; j < 4; j++) {
            int row = m0 + warp_m + i * 16 + row_g;
            int col = n0 + warp_n + j * 8 + col_g;
            float b0 = bias[col], b1 = bias[col + 1];
            float v00 = acc[i][j][0] + b0, v01 = acc[i][j][1] + b1;
            float v10 = acc[i][j][2] + b0, v11 = acc[i][j][3] + b1;
            if (BF16OUT) {
                __nv_bfloat162 h0 = __floats2bfloat162_rn(v00, v01);
                __nv_bfloat162 h1 = __floats2bfloat162_rn(v10, v11);
                __nv_bfloat162 l0 = __floats2bfloat162_rn(
                    v00 - __bfloat162float(h0.x), v01 - __bfloat162float(h0.y));
                __nv_bfloat162 l1 = __floats2bfloat162_rn(
                    v10 - __bfloat162float(h1.x), v11 - __bfloat162float(h1.y));
                *(__nv_bfloat162*)(Ch + (size_t)row * N + col) = h0;
                *(__nv_bfloat162*)(Ch + (size_t)(row + 8) * N + col) = h1;
                *(__nv_bfloat162*)(Cl + (size_t)row * N + col) = l0;
                *(__nv_bfloat162*)(Cl + (size_t)(row + 8) * N + col) = l1;
            } else {
                *(float2*)(C + (size_t)row * N + col) = make_float2(v00, v01);
                *(float2*)(C + (size_t)(row + 8) * N + col) = make_float2(v10, v11);
            }
        }
    }
}

// ---------------------------------------------------------------------------
// Tensor-core flash attention, bf16x3 split, fp32 accumulate.
// CTA = 64 q-rows x (b,h); 4 warps x 16 rows; 64-key tiles.
// K/V double-buffered via cp.async; Q fragments hoisted to registers.
// Writes GEMM2's augmented A matrix [hi|hi|lo] directly.
// ---------------------------------------------------------------------------
#define APITCH 72
#define ATILE (64 * APITCH)                 // elems per tile
#define ATT_SMEM ((2 + 8) * ATILE * 2)      // Q(h,l) + 2 stages x KV(h,l) = 92160 B

__global__ void __launch_bounds__(128) attn_tc(
    const __nv_bfloat16* __restrict__ qh, const __nv_bfloat16* __restrict__ ql,
    __nv_bfloat16* __restrict__ atts)
{
    extern __shared__ __nv_bfloat16 sm[];
    __nv_bfloat16* Qh = sm;
    __nv_bfloat16* Ql = Qh + ATILE;
    __nv_bfloat16* KV = Ql + ATILE;      // stage p: [Kh, Kl, Vh, Vl] each ATILE

    const int tid = threadIdx.x;
    const int wid = tid >> 5;
    const int lane = tid & 31;
    const int bh = blockIdx.y;
    const int b = bh >> 4, h = bh & 15;
    const int q0 = blockIdx.x * 64;
    const size_t tokbase = (size_t)b * SEQ;

    const uint32_t sQh = smem_u32(Qh), sQl = smem_u32(Ql);
    const uint32_t sKV = smem_u32(KV);

    // Load Q tile (hi, lo)
    {
        const size_t qoff = (tokbase + q0) * N_QKV + h * HDIM;
#pragma unroll
        for (int t = 0; t < 4; t++) {
            int idx = tid + t * 128;
            int row = idx >> 3;
            int ch = (idx & 7) * 8;
            *(uint4*)(Qh + row * APITCH + ch) = *(const uint4*)(qh + qoff + (size_t)row * N_QKV + ch);
            *(uint4*)(Ql + row * APITCH + ch) = *(const uint4*)(ql + qoff + (size_t)row * N_QKV + ch);
        }
    }

    auto load_kv = [&](int kt, int p) {
        const size_t koff = (tokbase + kt * 64) * N_QKV + HID + h * HDIM;
        const size_t voff = koff + HID;
        const uint32_t base = sKV + (uint32_t)p * (4 * ATILE * 2);
#pragma unroll
        for (int t = 0; t < 4; t++) {
            int idx = tid + t * 128;
            int row = idx >> 3;
            int ch = (idx & 7) * 8;
            size_t g = (size_t)row * N_QKV + ch;
            uint32_t doff = (uint32_t)((row * APITCH + ch) * 2);
            cp16(base + doff,                 qh + koff + g);
            cp16(base + ATILE * 2 + doff,     ql + koff + g);
            cp16(base + 2 * ATILE * 2 + doff, qh + voff + g);
            cp16(base + 3 * ATILE * 2 + doff, ql + voff + g);
        }
    };

    load_kv(0, 0);
    cp_commit();
    __syncthreads();   // Q stores visible

    const int lrow = lane & 15;
    const int lkh = (lane >> 4) * 8;
    const int vkey = (lane >> 4) * 8 + (lane & 7);
    const int vd = ((lane >> 3) & 1) * 8;

    // Hoist Q fragments (hi, lo) for all 4 k16 chunks
    uint32_t qfh[4][4], qfl[4][4];
#pragma unroll
    for (int kk = 0; kk < 4; kk++) {
        const uint32_t qoff2 = (uint32_t)(((wid * 16 + lrow) * APITCH + kk * 16 + lkh) * 2);
        ldm_x4(sQh + qoff2, qfh[kk][0], qfh[kk][1], qfh[kk][2], qfh[kk][3]);
        ldm_x4(sQl + qoff2, qfl[kk][0], qfl[kk][1], qfl[kk][2], qfl[kk][3]);
    }

    float m0 = -1e30f, m1 = -1e30f, l0 = 0.f, l1 = 0.f;
    float o[8][4];
#pragma unroll
    for (int t = 0; t < 8; t++)
#pragma unroll
        for (int q = 0; q < 4; q++) o[t][q] = 0.f;

    const int NK = SEQ / 64;
    for (int kt = 0; kt < NK; kt++) {
        const int p = kt & 1;
        cp_wait<0>();
        __syncthreads();
        if (kt + 1 < NK) load_kv(kt + 1, p ^ 1);
        cp_commit();

        const uint32_t base = sKV + (uint32_t)p * (4 * ATILE * 2);
        const uint32_t sKh = base;
        const uint32_t sKl = base + ATILE * 2;
        const uint32_t sVh = base + 2 * ATILE * 2;
        const uint32_t sVl = base + 3 * ATILE * 2;

        // ---- S = Q K^T (3-term split) ----
        float sf[8][4];
#pragma unroll
        for (int t = 0; t < 8; t++)
#pragma unroll
            for (int q = 0; q < 4; q++) sf[t][q] = 0.f;

#pragma unroll
        for (int kk = 0; kk < 4; kk++) {
#pragma unroll
            for (int jp = 0; jp < 4; jp++) {
                const uint32_t koff2 = (uint32_t)(((jp * 16 + lrow) * APITCH + kk * 16 + lkh) * 2);
                uint32_t h0, h1, h2, h3, e0, e1, e2, e3;
                ldm_x4(sKh + koff2, h0, h1, h2, h3);
                ldm_x4(sKl + koff2, e0, e1, e2, e3);
                mma_bf16(sf[2 * jp],     qfh[kk], h0, h2);
                mma_bf16(sf[2 * jp],     qfh[kk], e0, e2);
                mma_bf16(sf[2 * jp],     qfl[kk], h0, h2);
                mma_bf16(sf[2 * jp + 1], qfh[kk], h1, h3);
                mma_bf16(sf[2 * jp + 1], qfh[kk], e1, e3);
                mma_bf16(sf[2 * jp + 1], qfl[kk], h1, h3);
            }
        }

        // ---- online softmax ----
        float tm0 = -1e30f, tm1 = -1e30f;
#pragma unroll
        for (int t = 0; t < 8; t++) {
#pragma unroll
            for (int q = 0; q < 4; q++) sf[t][q] *= 0.125f;
            tm0 = fmaxf(tm0, fmaxf(sf[t][0], sf[t][1]));
            tm1 = fmaxf(tm1, fmaxf(sf[t][2], sf[t][3]));
        }
        tm0 = fmaxf(tm0, __shfl_xor_sync(0xffffffffu, tm0, 1));
        tm0 = fmaxf(tm0, __shfl_xor_sync(0xffffffffu, tm0, 2));
        tm1 = fmaxf(tm1, __shfl_xor_sync(0xffffffffu, tm1, 1));
        tm1 = fmaxf(tm1, __shfl_xor_sync(0xffffffffu, tm1, 2));

        float mn0 = fmaxf(m0, tm0), mn1 = fmaxf(m1, tm1);
        float a0 = __expf(m0 - mn0), a1 = __expf(m1 - mn1);
        m0 = mn0; m1 = mn1;

        float rs0 = 0.f, rs1 = 0.f;
#pragma unroll
        for (int t = 0; t < 8; t++) {
            sf[t][0] = __expf(sf[t][0] - mn0);
            sf[t][1] = __expf(sf[t][1] - mn0);
            sf[t][2] = __expf(sf[t][2] - mn1);
            sf[t][3] = __expf(sf[t][3] - mn1);
            rs0 += sf[t][0] + sf[t][1];
            rs1 += sf[t][2] + sf[t][3];
        }
        rs0 += __shfl_xor_sync(0xffffffffu, rs0, 1);
        rs0 += __shfl_xor_sync(0xffffffffu, rs0, 2);
        rs1 += __shfl_xor_sync(0xffffffffu, rs1, 1);
        rs1 += __shfl_xor_sync(0xffffffffu, rs1, 2);
        l0 = l0 * a0 + rs0;
        l1 = l1 * a1 + rs1;

#pragma unroll
        for (int t = 0; t < 8; t++) {
            o[t][0] *= a0; o[t][1] *= a0;
            o[t][2] *= a1; o[t][3] *= a1;
        }

        // ---- pack P into A-operand frags (hi + lo) ----
        uint32_t ph[4][4], pl[4][4];
#pragma unroll
        for (int kk = 0; kk < 4; kk++) {
            float* c0 = sf[2 * kk];
            float* c1 = sf[2 * kk + 1];
            ph[kk][0] = packbf(c0[0], c0[1]);
            ph[kk][1] = packbf(c0[2], c0[3]);
            ph[kk][2] = packbf(c1[0], c1[1]);
            ph[kk][3] = packbf(c1[2], c1[3]);
            __nv_bfloat162* hp;
            hp = (__nv_bfloat162*)&ph[kk][0];
            pl[kk][0] = packbf(c0[0] - __bfloat162float(hp->x), c0[1] - __bfloat162float(hp->y));
            hp = (__nv_bfloat162*)&ph[kk][1];
            pl[kk][1] = packbf(c0[2] - __bfloat162float(hp->x), c0[3] - __bfloat162float(hp->y));
            hp = (__nv_bfloat162*)&ph[kk][2];
            pl[kk][2] = packbf(c1[0] - __bfloat162float(hp->x), c1[1] - __bfloat162float(hp->y));
            hp = (__nv_bfloat162*)&ph[kk][3];
            pl[kk][3] = packbf(c1[2] - __bfloat162float(hp->x), c1[3] - __bfloat162float(hp->y));
        }

        // ---- O += P V (3-term split), V via ldmatrix.trans ----
#pragma unroll
        for (int kk = 0; kk < 4; kk++) {
#pragma unroll
            for (int dt = 0; dt < 4; dt++) {
                const uint32_t voff2 = (uint32_t)(((kk * 16 + vkey) * APITCH + dt * 16 + vd) * 2);
                uint32_t h0, h1, h2, h3, e0, e1, e2, e3;
                ldm_x4_t(sVh + voff2, h0, h1, h2, h3);
                ldm_x4_t(sVl + voff2, e0, e1, e2, e3);
                mma_bf16(o[2 * dt],     ph[kk], h0, h2);
                mma_bf16(o[2 * dt],     ph[kk], e0, e2);
                mma_bf16(o[2 * dt],     pl[kk], h0, h2);
                mma_bf16(o[2 * dt + 1], ph[kk], h1, h3);
                mma_bf16(o[2 * dt + 1], ph[kk], e1, e3);
                mma_bf16(o[2 * dt + 1], pl[kk], h1, h3);
            }
        }
    }

    // ---- epilogue: write augmented [hi|hi|lo] rows for GEMM2 ----
    const float inv0 = 1.f / l0, inv1 = 1.f / l1;
    const int gr0 = q0 + wid * 16 + (lane >> 2);
    const int gr1 = gr0 + 8;
    const size_t r0base = (tokbase + gr0) * (size_t)K3;
    const size_t r1base = (tokbase + gr1) * (size_t)K3;
#pragma unroll
    for (int t = 0; t < 8; t++) {
        int col = h * HDIM + t * 8 + (lane & 3) * 2;
        float v00 = o[t][0] * inv0, v01 = o[t][1] * inv0;
        float v10 = o[t][2] * inv1, v11 = o[t][3] * inv1;
        __nv_bfloat162 h0 = __floats2bfloat162_rn(v00, v01);
        __nv_bfloat162 h1 = __floats2bfloat162_rn(v10, v11);
        __nv_bfloat162 lo0 = __floats2bfloat162_rn(v00 - __bfloat162float(h0.x),
                                                   v01 - __bfloat162float(h0.y));
        __nv_bfloat162 lo1 = __floats2bfloat162_rn(v10 - __bfloat162float(h1.x),
                                                   v11 - __bfloat162float(h1.y));
        *(__nv_bfloat162*)(atts + r0base + col) = h0;
        *(__nv_bfloat162*)(atts + r0base + HID + col) = h0;
        *(__nv_bfloat162*)(atts + r0base + 2 * HID + col) = lo0;
        *(__nv_bfloat162*)(atts + r1base + col) = h1;
        *(__nv_bfloat162*)(atts + r1base + HID + col) = h1;
        *(__nv_bfloat162*)(atts + r1base + 2 * HID + col) = lo1;
    }
}

// ---------------------------------------------------------------------------
// Launch
// ---------------------------------------------------------------------------
extern "C" void kernel_launch(void* const* d_in, const int* in_sizes, int n_in,
                              void* d_out, int out_size)
{
    const float *x = nullptr, *w_qkv = nullptr, *b_qkv = nullptr,
                *w_out = nullptr, *b_out = nullptr;
    for (int i = 0; i < n_in; i++) {
        const float* p = (const float*)d_in[i];
        switch (in_sizes[i]) {
            case M_TOT * HID: x = p; break;
            case N_QKV * HID: w_qkv = p; break;
            case N_QKV:       b_qkv = p; break;
            case HID * HID:   w_out = p; break;
            case HID:         b_out = p; break;
        }
    }
    float* out = (float*)d_out;

    __nv_bfloat16 *qkvh, *qkvl, *xs, *wqkvs, *atts, *wouts;
    cudaGetSymbolAddress((void**)&qkvh, g_qkvh);
    cudaGetSymbolAddress((void**)&qkvl, g_qkvl);
    cudaGetSymbolAddress((void**)&xs, g_xs);
    cudaGetSymbolAddress((void**)&wqkvs, g_wqkvs);
    cudaGetSymbolAddress((void**)&atts, g_atts);
    cudaGetSymbolAddress((void**)&wouts, g_wouts);

    cudaFuncSetAttribute(attn_tc,
                         cudaFuncAttributeMaxDynamicSharedMemorySize, ATT_SMEM);
    cudaFuncSetAttribute(gemm_hmma<true>,
                         cudaFuncAttributeMaxDynamicSharedMemorySize, GEMM_SMEM);
    cudaFuncSetAttribute(gemm_hmma<false>,
                         cudaFuncAttributeMaxDynamicSharedMemorySize, GEMM_SMEM);

    dim3 blk(256);

    // Splits
    split_bf16<<<1024, blk>>>(x,     xs,    M_TOT, HID, 0);
    split_bf16<<<1024, blk>>>(w_qkv, wqkvs, N_QKV, HID, 1);
    split_bf16<<<1024, blk>>>(w_out, wouts, HID,   HID, 1);

    // GEMM1: qkv (bf16 hi/lo) = x @ w_qkv^T + b_qkv
    gemm_hmma<true><<<dim3(N_QKV / GBN, M_TOT / GBM), blk, GEMM_SMEM>>>(
        xs, wqkvs, b_qkv, nullptr, qkvh, qkvl, M_TOT, N_QKV, K3);

    // Attention (tensor-core): writes augmented A for GEMM2
    attn_tc<<<dim3(SEQ / 64, BATCH * NHEAD), dim3(128), ATT_SMEM>>>(qkvh, qkvl, atts);

    // GEMM2: out = att @ w_out^T + b_out
    gemm_hmma<false><<<dim3(HID / GBN, M_TOT / GBM), blk, GEMM_SMEM>>>(
        atts, wouts, b_out, out, nullptr, nullptr, M_TOT, HID, K3);
}